// round 14
// baseline (speedup 1.0000x reference)
#include <cuda_runtime.h>
#include <stdint.h>
#include <math.h>

// ---------------------------------------------------------------- constants
#define BATCH   2
#define NQ      16384
#define NATOMS  1024
#define KDIM    256
#define ODIM    256
#define NROWS   (BATCH * NQ)
#define OMEGA0  30.0f
#define EPSD    1e-4f

#define BM      64
#define BN      128
#define BKC     64
#define NCHUNK  (KDIM / BKC)     // 4
#define NTHREADS 512

#define OMEGA_CTAS 128           // each: 256 queries omega + 256 rows X-split
#define GEMM_CTAS  ((NROWS / BM) * (ODIM / BN))   // 1024

// quantization scales
#define SXF     2.0e-4f                       // x = SX*(256h + l), covers |x|<=6.52
#define IX256   19.53125f                     // 1/(SX*256)
static constexpr double WBOUND = 0.005103103630798288;   // sqrt(6/256)/30
static constexpr double SW_D   = WBOUND / 32600.0;
#define IW256   ((float)(1.0 / (SW_D * 256.0)))
#define C1F     ((float)(2.0e-4 * SW_D * 65536.0))
#define C2F     ((float)(2.0e-4 * SW_D * 256.0))

// SMEM map (GEMM): A ring 2 x 8K @0 ; B ring 2 x 16K @16384
// A stage: [h_s0 2K | h_s1 2K | l_s0 2K | l_s1 2K]   (64 rows x 32B, swz32)
// B stage: [h_s0 4K | h_s1 4K | l_s0 4K | l_s1 4K]   (128 rows x 32B, swz32)
#define OFF_A   0
#define OFF_B   16384
#define SM_BYTES 49152
#define EPI_STRIDE 132
#define PAD_PART 8208            // omega atom partitions

static __device__ uint8_t g_Wh8[ODIM * KDIM];
static __device__ uint8_t g_Wl8[ODIM * KDIM];
static __device__ uint8_t g_Xh8[NROWS * KDIM];
static __device__ uint8_t g_Xl8[NROWS * KDIM];
static __device__ float   g_omega[NROWS];
static __device__ int     g_flag;

// ---------------------------------------------------------------- helpers
__device__ __forceinline__ uint32_t smem_u32(const void* p) {
    uint32_t a;
    asm("{ .reg .u64 t; cvta.to.shared.u64 t, %1; cvt.u32.u64 %0, t; }" : "=r"(a) : "l"(p));
    return a;
}
__device__ __forceinline__ uint32_t swz32(uint32_t o) { return o ^ ((o >> 3) & 0x10); }

__device__ __forceinline__ void cp16(uint32_t dst, const void* src) {
    asm volatile("cp.async.cg.shared.global [%0], [%1], 16;" :: "r"(dst), "l"(src));
}
#define CP_COMMIT() asm volatile("cp.async.commit_group;")
#define CP_WAIT0()  asm volatile("cp.async.wait_group 0;")

#define LDSM4(r, a) \
    asm volatile("ldmatrix.sync.aligned.m8n8.x4.shared.b16 {%0,%1,%2,%3}, [%4];" \
        : "=r"((r)[0]), "=r"((r)[1]), "=r"((r)[2]), "=r"((r)[3]) : "r"(a))

#define IMMA(c, a, b0, b1) \
    asm volatile("mma.sync.aligned.m16n8k32.row.col.s32.s8.s8.s32 " \
        "{%0,%1,%2,%3},{%4,%5,%6,%7},{%8,%9},{%0,%1,%2,%3};" \
        : "+r"((c)[0]), "+r"((c)[1]), "+r"((c)[2]), "+r"((c)[3]) \
        : "r"((a)[0]), "r"((a)[1]), "r"((a)[2]), "r"((a)[3]), "r"(b0), "r"(b1))

// split 4 fp32 -> 4 s8 hi (packed u32) + 4 s8 lo
__device__ __forceinline__ uint32_t split4_s8(float4 v, float inv256, uint32_t& lo) {
    float t0 = v.x * inv256, t1 = v.y * inv256, t2 = v.z * inv256, t3 = v.w * inv256;
    int h0 = __float2int_rn(t0), h1 = __float2int_rn(t1);
    int h2 = __float2int_rn(t2), h3 = __float2int_rn(t3);
    h0 = max(-127, min(127, h0)); h1 = max(-127, min(127, h1));
    h2 = max(-127, min(127, h2)); h3 = max(-127, min(127, h3));
    int l0 = __float2int_rn((t0 - (float)h0) * 256.0f);
    int l1 = __float2int_rn((t1 - (float)h1) * 256.0f);
    int l2 = __float2int_rn((t2 - (float)h2) * 256.0f);
    int l3 = __float2int_rn((t3 - (float)h3) * 256.0f);
    l0 = max(-128, min(127, l0)); l1 = max(-128, min(127, l1));
    l2 = max(-128, min(127, l2)); l3 = max(-128, min(127, l3));
    lo = __byte_perm(__byte_perm(l0, l1, 0x0040), __byte_perm(l2, l3, 0x0040), 0x5410);
    return __byte_perm(__byte_perm(h0, h1, 0x0040), __byte_perm(h2, h3, 0x0040), 0x5410);
}

// ---------------------------------------------------------------- prep: W split + flag reset
__global__ __launch_bounds__(256)
void prep_w(const float* __restrict__ W)
{
    if (blockIdx.x == 0 && threadIdx.x == 0) g_flag = 0;
    int u = blockIdx.x * 256 + threadIdx.x;      // float4 index over 65536 floats
    float4 v = ((const float4*)W)[u];
    uint32_t lo;
    uint32_t hi = split4_s8(v, IW256, lo);
    ((uint32_t*)g_Wh8)[u] = hi;
    ((uint32_t*)g_Wl8)[u] = lo;
}

// ---------------------------------------------------------------- main kernel
__global__ __launch_bounds__(NTHREADS, 2)
void siren_main(const float* __restrict__ X, const float* __restrict__ Q,
                const float* __restrict__ atoms, const float* __restrict__ bias,
                const float* __restrict__ fw1, const float* __restrict__ fb1,
                const float* __restrict__ fw2, const float* __restrict__ fb2,
                float* __restrict__ out)
{
    extern __shared__ char sb[];
    const uint32_t sbase = smem_u32(sb);
    const int tid = threadIdx.x;

    // ============== wave-1 CTAs: omega + X s8-split for 256 rows ==============
    if (blockIdx.x < OMEGA_CTAS) {
        const int q0 = blockIdx.x * 256;
        const int batch = (q0 >= NQ) ? 1 : 0;
        const float* ab = atoms + (size_t)batch * NATOMS * 3;
        for (int j = tid; j < NATOMS; j += NTHREADS) {
            float ax = ab[3*j], ay = ab[3*j+1], az = ab[3*j+2];
            *(float4*)(sb + (j >> 9) * PAD_PART + (j & 511) * 16) =
                make_float4(ax, ay, az, fmaf(ax, ax, fmaf(ay, ay, az*az)));
        }
        __syncthreads();

        // omega: 2 threads per query
        {
            const int qi = q0 + (tid >> 1);
            const int part = tid & 1;
            const float* qp = Q + (size_t)qi * 3;
            float qx = qp[0], qy = qp[1], qz = qp[2];
            float nqx = -2.f * qx, nqy = -2.f * qy, nqz = -2.f * qz;
            const float4* at = (const float4*)(sb + part * PAD_PART);
            float m0 = 3.4e38f, m1 = 3.4e38f;
#pragma unroll 4
            for (int j = 0; j < 512; j += 2) {
                float4 a0 = at[j], a1 = at[j + 1];
                m0 = fminf(m0, fmaf(a0.x, nqx, fmaf(a0.y, nqy, fmaf(a0.z, nqz, a0.w))));
                m1 = fminf(m1, fmaf(a1.x, nqx, fmaf(a1.y, nqy, fmaf(a1.z, nqz, a1.w))));
            }
            float md = fminf(m0, m1);
            md = fminf(md, __shfl_xor_sync(0xffffffffu, md, 1));
            if (part == 0) {
                float qsq = fmaf(qx, qx, fmaf(qy, qy, qz * qz));
                float mind = sqrtf(fmaxf(md + qsq, EPSD));
                float ls = __ldg(fb2);
#pragma unroll
                for (int j = 0; j < 16; ++j) {
                    float z = fmaf(__ldg(fw1 + 3*j), qx,
                              fmaf(__ldg(fw1 + 3*j + 1), qy,
                              fmaf(__ldg(fw1 + 3*j + 2), qz, __ldg(fb1 + j))));
                    float sp = fmaxf(z, 0.0f) + log1pf(expf(-fabsf(z)));
                    ls = fmaf(__ldg(fw2 + j), sp, ls);
                }
                ls = fminf(fmaxf(ls, 0.0f), 5.0f);
                g_omega[qi] = OMEGA0 * (1.0f + ls * expf(-mind));
            }
        }

        // X split: rows [q0, q0+256), 16384 float4 units
        {
            const float4* Xs = (const float4*)(X + (size_t)q0 * KDIM);
            uint32_t* Hp = (uint32_t*)(g_Xh8 + (size_t)q0 * KDIM);
            uint32_t* Lp = (uint32_t*)(g_Xl8 + (size_t)q0 * KDIM);
#pragma unroll 4
            for (int i = 0; i < 32; ++i) {
                int u = tid + i * NTHREADS;
                float4 v = Xs[u];
                uint32_t lo;
                uint32_t hi = split4_s8(v, IX256, lo);
                Hp[u] = hi;
                Lp[u] = lo;
            }
        }
        __threadfence();
        __syncthreads();
        if (tid == 0) atomicAdd(&g_flag, 1);
        return;
    }

    // ============== GEMM CTAs: 64 rows x 128 cols, int8 2-pass ==============
    const int bid  = blockIdx.x - OMEGA_CTAS;
    const int lane = tid & 31;
    const int wid  = tid >> 5;
    const int gRow0 = (bid >> 1) * BM;
    const int gCol0 = (bid & 1) * BN;

    const int warpM = (wid & 3) * 16;        // 4 M-groups of 16
    const int warpN = (wid >> 2) * 32;       // 4 N-groups of 32
    const int lr = lane >> 2;
    const int lc = (lane & 3) * 2;
    const int l7 = lane & 7, g = lane >> 3;
    const uint32_t aoff = swz32((uint32_t)((warpM + l7 + (g & 1) * 8) * 32 + ((g >> 1) & 1) * 16));
    const uint32_t boff = swz32((uint32_t)((warpN + l7 + ((g >> 1) & 1) * 8) * 32 + (g & 1) * 16));

    // wait for omega/X-split CTAs (wave-1) before touching g_X*8
    if (tid == 0) {
        int v;
        do {
            asm volatile("ld.acquire.gpu.global.b32 %0, [%1];" : "=r"(v) : "l"(&g_flag));
        } while (v < OMEGA_CTAS);
    }
    __syncthreads();

    auto prefAB = [&](int c) {
        const uint32_t st = (uint32_t)(c & 1);
        {   // B hi + lo: 512 units each, 1 per thread per matrix
            int n = tid >> 2, kq = tid & 3;
            uint32_t d = sbase + OFF_B + st * 16384 + (kq >> 1) * 4096
                       + (swz32((uint32_t)(n * 32)) ^ (uint32_t)((kq & 1) * 16));
            size_t gs = (size_t)(gCol0 + n) * KDIM + c * BKC + kq * 16;
            cp16(d,        g_Wh8 + gs);
            cp16(d + 8192, g_Wl8 + gs);
        }
        {   // A hi (threads 0-255) / lo (256-511): 256 units each
            int m = tid & 255, mat = tid >> 8;
            int row = m >> 2, kq = m & 3;
            uint32_t d = sbase + OFF_A + st * 8192 + mat * 4096 + (kq >> 1) * 2048
                       + (swz32((uint32_t)(row * 32)) ^ (uint32_t)((kq & 1) * 16));
            const uint8_t* base = mat ? g_Xl8 : g_Xh8;
            cp16(d, base + (size_t)(gRow0 + row) * KDIM + c * BKC + kq * 16);
        }
    };

    prefAB(0);
    CP_COMMIT();

    int acc1[4][4], acc2[4][4];
#pragma unroll
    for (int j = 0; j < 4; ++j)
#pragma unroll
        for (int k = 0; k < 4; ++k) { acc1[j][k] = 0; acc2[j][k] = 0; }

    // ---- main loop: 4 chunks of K64 (2 k32 steps each) ----
#pragma unroll 1
    for (int c = 0; c < NCHUNK; ++c) {
        CP_WAIT0();
        __syncthreads();
        if (c + 1 < NCHUNK) { prefAB(c + 1); CP_COMMIT(); }

        const uint32_t Ast = sbase + OFF_A + (uint32_t)(c & 1) * 8192;
        const uint32_t Bst = sbase + OFF_B + (uint32_t)(c & 1) * 16384;
#pragma unroll
        for (int s = 0; s < 2; ++s) {
            const uint32_t aA = Ast + s * 2048 + aoff;
            const uint32_t bA = Bst + s * 4096 + boff;
            uint32_t ah[4], al[4], bq[2][4];
            LDSM4(ah, aA);
            LDSM4(al, aA + 4096);
            LDSM4(bq[0], bA);
            LDSM4(bq[1], bA + 512);
            // hh -> acc1 ; lh -> acc2
#pragma unroll
            for (int p = 0; p < 2; ++p) {
                IMMA(acc1[2*p],   ah, bq[p][0], bq[p][1]);
                IMMA(acc1[2*p+1], ah, bq[p][2], bq[p][3]);
            }
#pragma unroll
            for (int p = 0; p < 2; ++p) {
                IMMA(acc2[2*p],   al, bq[p][0], bq[p][1]);
                IMMA(acc2[2*p+1], al, bq[p][2], bq[p][3]);
            }
            // hl -> acc2 (reload B as lo)
            LDSM4(bq[0], bA + 8192);
            LDSM4(bq[1], bA + 8192 + 512);
#pragma unroll
            for (int p = 0; p < 2; ++p) {
                IMMA(acc2[2*p],   ah, bq[p][0], bq[p][1]);
                IMMA(acc2[2*p+1], ah, bq[p][2], bq[p][3]);
            }
        }
    }
    __syncthreads();            // all tile reads done; smem free for staging

    // ---- epilogue: pre = C1*hh + C2*cross; out = sin(omega*(pre+bias)) ----
    float* stg = (float*)sb;
    {
        int r0 = warpM + lr;
        float o0 = __ldg(g_omega + gRow0 + r0);
        float o1 = __ldg(g_omega + gRow0 + r0 + 8);
#pragma unroll
        for (int nt = 0; nt < 4; ++nt) {
            int c0 = warpN + nt * 8 + lc;
            float b0 = __ldg(bias + gCol0 + c0), b1 = __ldg(bias + gCol0 + c0 + 1);
            float p0 = fmaf((float)acc1[nt][0], C1F, (float)acc2[nt][0] * C2F);
            float p1 = fmaf((float)acc1[nt][1], C1F, (float)acc2[nt][1] * C2F);
            float p2 = fmaf((float)acc1[nt][2], C1F, (float)acc2[nt][2] * C2F);
            float p3 = fmaf((float)acc1[nt][3], C1F, (float)acc2[nt][3] * C2F);
            *(float2*)(stg + r0 * EPI_STRIDE + c0) =
                make_float2(__sinf(o0 * (p0 + b0)), __sinf(o0 * (p1 + b1)));
            *(float2*)(stg + (r0 + 8) * EPI_STRIDE + c0) =
                make_float2(__sinf(o1 * (p2 + b0)), __sinf(o1 * (p3 + b1)));
        }
    }
    __syncthreads();
#pragma unroll
    for (int i = 0; i < 4; ++i) {
        int lin = tid + i * NTHREADS;          // float4 over 64x128
        int rr = lin >> 5, c4 = (lin & 31) * 4;
        *(float4*)(out + (size_t)(gRow0 + rr) * ODIM + gCol0 + c4) =
            *(const float4*)(stg + rr * EPI_STRIDE + c4);
    }
}

// ---------------------------------------------------------------- launch
extern "C" void kernel_launch(void* const* d_in, const int* in_sizes, int n_in,
                              void* d_out, int out_size)
{
    const float* x     = (const float*)d_in[0];
    const float* q     = (const float*)d_in[1];
    const float* atoms = (const float*)d_in[2];
    const float* W     = (const float*)d_in[3];
    const float* bias  = (const float*)d_in[4];
    const float* fw1   = (const float*)d_in[5];
    const float* fb1   = (const float*)d_in[6];
    const float* fw2   = (const float*)d_in[7];
    const float* fb2   = (const float*)d_in[8];
    float* out = (float*)d_out;
    (void)in_sizes; (void)n_in; (void)out_size;

    cudaFuncSetAttribute(siren_main, cudaFuncAttributeMaxDynamicSharedMemorySize, SM_BYTES);

    prep_w<<<(ODIM * KDIM / 4) / 256, 256>>>(W);
    siren_main<<<OMEGA_CTAS + GEMM_CTAS, NTHREADS, SM_BYTES>>>(
        x, q, atoms, bias, fw1, fb1, fw2, fb2, out);
}

// round 15
// speedup vs baseline: 1.9585x; 1.9585x over previous
#include <cuda_runtime.h>
#include <cuda_bf16.h>
#include <stdint.h>
#include <math.h>

// ---------------------------------------------------------------- constants
#define BATCH   2
#define NQ      16384
#define NATOMS  1024
#define KDIM    256
#define ODIM    256
#define NROWS   (BATCH * NQ)
#define OMEGA0  30.0f
#define EPSD    1e-4f

#define BM      128
#define BN      128
#define BKC     32
#define NCHUNK  (KDIM / BKC)     // 8
#define NTHREADS 256

#define OMEGA_CTAS 256           // 128 queries each
#define GEMM_CTAS  ((NROWS / BM) * (ODIM / BN))   // 512

// SMEM: A ring 2 x 16KB @0, B ring 2 x 16KB @32768.
// Stage layout (A and B identical): slice s(k16) block 8KB at s*8192 = [hi 4K | lo 4K].
// Rows are 32B, swizzled XOR bit7->bit4.
#define OFF_A   0
#define OFF_B   32768
#define SM_BYTES 67584           // epilogue staging 128 x 132 floats
#define EPI_STRIDE 132
#define PAD_PART 8208            // omega atom partitions (512 float4 + 16B pad)

static __device__ __nv_bfloat16 g_Whi[ODIM * KDIM];
static __device__ __nv_bfloat16 g_Wlo[ODIM * KDIM];
static __device__ float         g_omega[NROWS];
static __device__ int           g_flag;

// ---------------------------------------------------------------- helpers
__device__ __forceinline__ uint32_t smem_u32(const void* p) {
    uint32_t a;
    asm("{ .reg .u64 t; cvta.to.shared.u64 t, %1; cvt.u32.u64 %0, t; }" : "=r"(a) : "l"(p));
    return a;
}
__device__ __forceinline__ uint32_t swz32(uint32_t o) { return o ^ ((o >> 3) & 0x10); }

__device__ __forceinline__ void sts_u4(uint32_t a, uint32_t x, uint32_t y,
                                       uint32_t z, uint32_t w) {
    asm volatile("st.shared.v4.b32 [%0], {%1,%2,%3,%4};" :: "r"(a), "r"(x), "r"(y), "r"(z), "r"(w));
}
__device__ __forceinline__ void cp16(uint32_t dst, const void* src) {
    asm volatile("cp.async.cg.shared.global [%0], [%1], 16;" :: "r"(dst), "l"(src));
}
#define CP_COMMIT() asm volatile("cp.async.commit_group;")
#define CP_WAIT0()  asm volatile("cp.async.wait_group 0;")

#define LDSM4(r, a) \
    asm volatile("ldmatrix.sync.aligned.m8n8.x4.shared.b16 {%0,%1,%2,%3}, [%4];" \
        : "=r"((r)[0]), "=r"((r)[1]), "=r"((r)[2]), "=r"((r)[3]) : "r"(a))

__device__ __forceinline__ void mma_bf16(float* c, const uint32_t* a,
                                         uint32_t b0, uint32_t b1) {
    asm volatile(
        "mma.sync.aligned.m16n8k16.row.col.f32.bf16.bf16.f32 "
        "{%0,%1,%2,%3}, {%4,%5,%6,%7}, {%8,%9}, {%0,%1,%2,%3};"
        : "+f"(c[0]), "+f"(c[1]), "+f"(c[2]), "+f"(c[3])
        : "r"(a[0]), "r"(a[1]), "r"(a[2]), "r"(a[3]), "r"(b0), "r"(b1));
}
__device__ __forceinline__ uint32_t packsplit(float x, float y, uint32_t& lo) {
    uint32_t h;
    asm("cvt.rn.bf16x2.f32 %0, %1, %2;" : "=r"(h) : "f"(y), "f"(x));
    float hx = __uint_as_float(h << 16);
    float hy = __uint_as_float(h & 0xffff0000u);
    float rx = x - hx, ry = y - hy;
    asm("cvt.rn.bf16x2.f32 %0, %1, %2;" : "=r"(lo) : "f"(ry), "f"(rx));
    return h;
}

// ---------------------------------------------------------------- prep: W split + flag reset
__global__ __launch_bounds__(256)
void prep_w(const float* __restrict__ W)
{
    if (blockIdx.x == 0 && threadIdx.x == 0) g_flag = 0;
    int i = blockIdx.x * 256 + threadIdx.x;
    float w = W[i];
    __nv_bfloat16 h = __float2bfloat16(w);
    g_Whi[i] = h;
    g_Wlo[i] = __float2bfloat16(w - __bfloat162float(h));
}

// ---------------------------------------------------------------- main: omega CTAs + GEMM CTAs
__global__ __launch_bounds__(NTHREADS, 2)
void siren_main(const float* __restrict__ X, const float* __restrict__ Q,
                const float* __restrict__ atoms, const float* __restrict__ bias,
                const float* __restrict__ fw1, const float* __restrict__ fb1,
                const float* __restrict__ fw2, const float* __restrict__ fb2,
                float* __restrict__ out)
{
    extern __shared__ char sb[];
    const uint32_t sbase = smem_u32(sb);
    const int tid = threadIdx.x;

    // ================= omega CTAs (first waves): 128 queries each =================
    if (blockIdx.x < OMEGA_CTAS) {
        const int q0 = blockIdx.x * 128;
        const int batch = (q0 >= NQ) ? 1 : 0;
        const float* ab = atoms + (size_t)batch * NATOMS * 3;
        for (int j = tid; j < NATOMS; j += NTHREADS) {
            float ax = ab[3*j], ay = ab[3*j+1], az = ab[3*j+2];
            *(float4*)(sb + (j >> 9) * PAD_PART + (j & 511) * 16) =
                make_float4(ax, ay, az, fmaf(ax, ax, fmaf(ay, ay, az*az)));
        }
        __syncthreads();

        const int qi = q0 + (tid >> 1);
        const int part = tid & 1;
        const float* qp = Q + (size_t)qi * 3;
        float qx = qp[0], qy = qp[1], qz = qp[2];
        float nqx = -2.f * qx, nqy = -2.f * qy, nqz = -2.f * qz;
        const float4* at = (const float4*)(sb + part * PAD_PART);
        float m0 = 3.4e38f, m1 = 3.4e38f;
#pragma unroll 4
        for (int j = 0; j < 512; j += 2) {
            float4 a0 = at[j], a1 = at[j + 1];
            m0 = fminf(m0, fmaf(a0.x, nqx, fmaf(a0.y, nqy, fmaf(a0.z, nqz, a0.w))));
            m1 = fminf(m1, fmaf(a1.x, nqx, fmaf(a1.y, nqy, fmaf(a1.z, nqz, a1.w))));
        }
        float md = fminf(m0, m1);
        md = fminf(md, __shfl_xor_sync(0xffffffffu, md, 1));
        if (part == 0) {
            float qsq = fmaf(qx, qx, fmaf(qy, qy, qz * qz));
            float mind = sqrtf(fmaxf(md + qsq, EPSD));
            float ls = __ldg(fb2);
#pragma unroll
            for (int j = 0; j < 16; ++j) {
                float z = fmaf(__ldg(fw1 + 3*j), qx,
                          fmaf(__ldg(fw1 + 3*j + 1), qy,
                          fmaf(__ldg(fw1 + 3*j + 2), qz, __ldg(fb1 + j))));
                float sp = fmaxf(z, 0.0f) + log1pf(expf(-fabsf(z)));
                ls = fmaf(__ldg(fw2 + j), sp, ls);
            }
            ls = fminf(fmaxf(ls, 0.0f), 5.0f);
            g_omega[qi] = OMEGA0 * (1.0f + ls * expf(-mind));
        }
        __threadfence();
        __syncthreads();
        if (tid == 0) atomicAdd(&g_flag, 1);
        return;
    }

    // ================= GEMM CTAs: 128x128, 8 warps (4M x 2N), warp tile 32x64 ==========
    const int bid  = blockIdx.x - OMEGA_CTAS;
    const int lane = tid & 31;
    const int wid  = tid >> 5;
    const int gRow0 = (bid >> 1) * BM;
    const int gCol0 = (bid & 1) * BN;

    const int warpM = (wid & 3) * 32;        // 4 M-groups of 32
    const int warpN = (wid >> 2) * 64;       // 2 N-groups of 64
    const int lr = lane >> 2;
    const int lc = (lane & 3) * 2;
    const int l7 = lane & 7, g = lane >> 3;
    const uint32_t aoff = swz32((uint32_t)((warpM + l7 + (g & 1) * 8) * 32 + ((g >> 1) & 1) * 16));
    const uint32_t boff = swz32((uint32_t)((warpN + l7 + (g >> 1) * 8) * 32 + (g & 1) * 16));

    // X loader: row r = tid>>1, k-slice h = tid&1 (16 floats/thread per chunk)
    const int xr = tid >> 1, xh = tid & 1;
    const float* Xrow = X + (size_t)(gRow0 + xr) * KDIM + xh * 16;

    auto prefB = [&](int c) {   // 16KB hi+lo per chunk, 4 cp16/thread
#pragma unroll
        for (int i = 0; i < 2; ++i) {
            int u = tid + i * NTHREADS;          // 0..511
            int n = u >> 2, kq = u & 3;
            int s = kq >> 1, e = kq & 1;
            uint32_t d = sbase + OFF_B + (uint32_t)(c & 1) * 16384 + s * 8192
                       + (swz32((uint32_t)(n * 32)) ^ (uint32_t)(e * 16));
            const int gs = (gCol0 + n) * KDIM + c * BKC + s * 16 + e * 8;
            cp16(d,        g_Whi + gs);
            cp16(d + 4096, g_Wlo + gs);
        }
    };
    // split 16 fp32 (registers) -> A stage (c&1), slice xh, row xr
    auto storeA = [&](int c, const float4* xv) {
        uint32_t h[8], l[8];
#pragma unroll
        for (int i = 0; i < 4; ++i) {
            h[2*i]   = packsplit(xv[i].x, xv[i].y, l[2*i]);
            h[2*i+1] = packsplit(xv[i].z, xv[i].w, l[2*i+1]);
        }
        uint32_t base = sbase + OFF_A + (uint32_t)(c & 1) * 16384 + xh * 8192
                      + swz32((uint32_t)(xr * 32));
        sts_u4(base,             h[0], h[1], h[2], h[3]);
        sts_u4(base ^ 16,        h[4], h[5], h[6], h[7]);
        sts_u4(base + 4096,      l[0], l[1], l[2], l[3]);
        sts_u4((base + 4096) ^ 16, l[4], l[5], l[6], l[7]);
    };

    // ---- prologue: B(0) via cp.async; X(0) via LDG -> A(0) ----
    prefB(0);
    CP_COMMIT();
    {
        float4 xv[4];
#pragma unroll
        for (int i = 0; i < 4; ++i) xv[i] = *(const float4*)(Xrow + i * 4);
        storeA(0, xv);
    }

    float acc[2][8][4];
#pragma unroll
    for (int i = 0; i < 2; ++i)
#pragma unroll
        for (int j = 0; j < 8; ++j)
#pragma unroll
            for (int k = 0; k < 4; ++k) acc[i][j][k] = 0.0f;

    // ---- main loop. Race-free: stage overwrites (prefB/storeA for c+1) touch
    // the stage last read in iteration c-1, and the iteration-c barrier separates
    // those reads from these writes.
#pragma unroll 1
    for (int c = 0; c < NCHUNK; ++c) {
        CP_WAIT0();             // B(c) landed (group committed in iter c-1)
        __syncthreads();        // publish A(c) (stored at end of c-1) + all reads
        if (c + 1 < NCHUNK) { prefB(c + 1); CP_COMMIT(); }

        float4 xv[4];
        if (c + 1 < NCHUNK) {
            const float* Xn = Xrow + (c + 1) * BKC;
#pragma unroll
            for (int i = 0; i < 4; ++i) xv[i] = *(const float4*)(Xn + i * 4);
        }

        const uint32_t Ast = sbase + OFF_A + (uint32_t)(c & 1) * 16384;
        const uint32_t Bst = sbase + OFF_B + (uint32_t)(c & 1) * 16384;
#pragma unroll
        for (int s = 0; s < 2; ++s) {
            const uint32_t ab = Ast + s * 8192 + aoff;
            const uint32_t bb = Bst + s * 8192 + boff;
            uint32_t ah[2][4], al[2][4], bq[4][4];
            LDSM4(ah[0], ab);
            LDSM4(ah[1], ab + 512);
            LDSM4(al[0], ab + 4096);
            LDSM4(al[1], ab + 4096 + 512);
#pragma unroll
            for (int p = 0; p < 4; ++p) LDSM4(bq[p], bb + p * 512);
            // pass 1: hi*HI
#pragma unroll
            for (int mt = 0; mt < 2; ++mt)
#pragma unroll
                for (int p = 0; p < 4; ++p) {
                    mma_bf16(acc[mt][2*p],   ah[mt], bq[p][0], bq[p][1]);
                    mma_bf16(acc[mt][2*p+1], ah[mt], bq[p][2], bq[p][3]);
                }
            // pass 2: lo*HI
#pragma unroll
            for (int mt = 0; mt < 2; ++mt)
#pragma unroll
                for (int p = 0; p < 4; ++p) {
                    mma_bf16(acc[mt][2*p],   al[mt], bq[p][0], bq[p][1]);
                    mma_bf16(acc[mt][2*p+1], al[mt], bq[p][2], bq[p][3]);
                }
            // pass 3: hi*LO
#pragma unroll
            for (int p = 0; p < 4; ++p) LDSM4(bq[p], bb + 4096 + p * 512);
#pragma unroll
            for (int mt = 0; mt < 2; ++mt)
#pragma unroll
                for (int p = 0; p < 4; ++p) {
                    mma_bf16(acc[mt][2*p],   ah[mt], bq[p][0], bq[p][1]);
                    mma_bf16(acc[mt][2*p+1], ah[mt], bq[p][2], bq[p][3]);
                }
        }
        if (c + 1 < NCHUNK) storeA(c + 1, xv);
    }
    __syncthreads();            // all tile reads done; smem free

    // ---- wait for omega CTAs ----
    if (tid == 0) {
        int v;
        do {
            asm volatile("ld.acquire.gpu.global.b32 %0, [%1];" : "=r"(v) : "l"(&g_flag));
        } while (v < OMEGA_CTAS);
    }
    __syncthreads();

    // ---- epilogue: sin(omega*(acc+bias)) -> SMEM -> coalesced STG ----
    float* stg = (float*)sb;
#pragma unroll
    for (int mt = 0; mt < 2; ++mt) {
        int r0 = warpM + mt * 16 + lr;
        float o0 = __ldg(g_omega + gRow0 + r0);
        float o1 = __ldg(g_omega + gRow0 + r0 + 8);
#pragma unroll
        for (int nt = 0; nt < 8; ++nt) {
            int c0 = warpN + nt * 8 + lc;
            float b0 = __ldg(bias + gCol0 + c0), b1 = __ldg(bias + gCol0 + c0 + 1);
            float* a = acc[mt][nt];
            *(float2*)(stg + r0 * EPI_STRIDE + c0) =
                make_float2(__sinf(o0 * (a[0] + b0)), __sinf(o0 * (a[1] + b1)));
            *(float2*)(stg + (r0 + 8) * EPI_STRIDE + c0) =
                make_float2(__sinf(o1 * (a[2] + b0)), __sinf(o1 * (a[3] + b1)));
        }
    }
    __syncthreads();
#pragma unroll
    for (int i = 0; i < 16; ++i) {
        int lin = tid + i * NTHREADS;
        int rr = lin >> 5, c4 = (lin & 31) * 4;
        *(float4*)(out + (size_t)(gRow0 + rr) * ODIM + gCol0 + c4) =
            *(const float4*)(stg + rr * EPI_STRIDE + c4);
    }
}

// ---------------------------------------------------------------- launch
extern "C" void kernel_launch(void* const* d_in, const int* in_sizes, int n_in,
                              void* d_out, int out_size)
{
    const float* x     = (const float*)d_in[0];
    const float* q     = (const float*)d_in[1];
    const float* atoms = (const float*)d_in[2];
    const float* W     = (const float*)d_in[3];
    const float* bias  = (const float*)d_in[4];
    const float* fw1   = (const float*)d_in[5];
    const float* fb1   = (const float*)d_in[6];
    const float* fw2   = (const float*)d_in[7];
    const float* fb2   = (const float*)d_in[8];
    float* out = (float*)d_out;
    (void)in_sizes; (void)n_in; (void)out_size;

    cudaFuncSetAttribute(siren_main, cudaFuncAttributeMaxDynamicSharedMemorySize, SM_BYTES);

    prep_w<<<(ODIM * KDIM) / 256, 256>>>(W);
    siren_main<<<OMEGA_CTAS + GEMM_CTAS, NTHREADS, SM_BYTES>>>(
        x, q, atoms, bias, fw1, fb1, fw2, fb2, out);
}